// round 3
// baseline (speedup 1.0000x reference)
#include <cuda_runtime.h>
#include <math.h>
#include <stdint.h>

// ---------------------------------------------------------------------------
// Problem constants
// ---------------------------------------------------------------------------
#define N_NODES 50000
#define N_EDGES 10000
#define NNZ     400000
#define QDIM    128
#define VDIM    256
#define EDIM    256
#define KIN     256
#define NEG_SLOPE 0.01f
#define SCORE_SCALE 0.08838834764831845f   // 1/sqrt(128)

// ---------------------------------------------------------------------------
// Static scratch (no allocation allowed)
// ---------------------------------------------------------------------------
__device__ float g_feat_v[N_NODES * VDIM];
__device__ float g_k1[N_NODES * QDIM];
__device__ float g_v1[N_NODES * EDIM];
__device__ float g_q2[N_NODES * QDIM];
__device__ float g_q1[N_EDGES * QDIM];
__device__ float g_k2[N_EDGES * QDIM];
__device__ float g_v2[N_EDGES * VDIM];
__device__ float g_score[NNZ];
__device__ float g_expw[NNZ];
__device__ float g_segmax[N_NODES];
__device__ float g_segsum[N_NODES];
__device__ int   g_counts[N_NODES];
__device__ int   g_offsets[N_NODES + 1];
__device__ int   g_cursor[N_NODES];
__device__ int   g_perm[NNZ];
__device__ int   g_partials[64];

// ---------------------------------------------------------------------------
// 3xTF32 tensor-core GEMM: C[M,N] = A[M,K] @ W[N,K]^T + bias[N]
// Block 128x128, BK=16, 128 threads = 4 warps (2x2), warp tile 64x64.
// hi/lo tf32 packed as uint2 in smem -> LDS.64 fragment loads (conflict-free
// with row stride 20 in 8B units). Pass-major mma order (hh, hl, lh) keeps
// accumulator RAW reuse distance at 16 instructions.
// Requires N % 128 == 0, K % 16 == 0 (true for all calls). M guarded.
// ---------------------------------------------------------------------------
#define BM 128
#define BN 128
#define BK 16
#define SS2 20   // row stride in uint2 units

__device__ __forceinline__ uint32_t f2tf(float x)
{
    uint32_t r;
    asm("cvt.rna.tf32.f32 %0, %1;" : "=r"(r) : "f"(x));
    return r;
}

__device__ __forceinline__ void mma_tf32(float* c,
    uint32_t a0, uint32_t a1, uint32_t a2, uint32_t a3,
    uint32_t b0, uint32_t b1)
{
    asm volatile(
        "mma.sync.aligned.m16n8k8.row.col.f32.tf32.tf32.f32 "
        "{%0,%1,%2,%3}, {%4,%5,%6,%7}, {%8,%9}, {%0,%1,%2,%3};"
        : "+f"(c[0]), "+f"(c[1]), "+f"(c[2]), "+f"(c[3])
        : "r"(a0), "r"(a1), "r"(a2), "r"(a3), "r"(b0), "r"(b1));
}

__global__ __launch_bounds__(128) void gemm_tf32_kernel(
    const float* __restrict__ A, const float* __restrict__ W,
    const float* __restrict__ bias, float* __restrict__ C,
    int M, int N, int K)
{
    __shared__ uint2 As2[BM][SS2];   // 20 KB
    __shared__ uint2 Bs2[BN][SS2];   // 20 KB

    const int t    = threadIdx.x;
    const int lane = t & 31;
    const int wid  = t >> 5;
    const int wm   = wid & 1;    // warp m (0..1), 64 rows
    const int wn   = wid >> 1;   // warp n (0..1), 64 cols
    const int g    = lane >> 2;
    const int t4   = lane & 3;

    const int block_m = blockIdx.y * BM;
    const int block_n = blockIdx.x * BN;

    // per-thread staging row (clamped; garbage rows never mix into valid rows)
    const int gm = block_m + t;
    const float* arow = A + (size_t)(gm < M ? gm : (M - 1)) * K;
    const float* wrow = W + (size_t)(block_n + t) * K;

    float acc[4][8][4];
#pragma unroll
    for (int i = 0; i < 4; i++)
#pragma unroll
        for (int j = 0; j < 8; j++)
#pragma unroll
            for (int l = 0; l < 4; l++) acc[i][j][l] = 0.f;

    float4 pa[4], pb[4];
#pragma unroll
    for (int u = 0; u < 4; u++) {
        pa[u] = *(const float4*)(arow + u * 4);
        pb[u] = *(const float4*)(wrow + u * 4);
    }

    for (int k0 = 0; k0 < K; k0 += BK) {
        // ---- stage current tile: cvt hi/lo, STS.128 pairs ----
#pragma unroll
        for (int u = 0; u < 4; u++) {
            const float av[4] = {pa[u].x, pa[u].y, pa[u].z, pa[u].w};
            const float bv[4] = {pb[u].x, pb[u].y, pb[u].z, pb[u].w};
#pragma unroll
            for (int p = 0; p < 2; p++) {
                const float a0 = av[p * 2], a1 = av[p * 2 + 1];
                uint32_t ah0 = f2tf(a0), ah1 = f2tf(a1);
                uint32_t al0 = f2tf(a0 - __uint_as_float(ah0));
                uint32_t al1 = f2tf(a1 - __uint_as_float(ah1));
                *(uint4*)&As2[t][u * 4 + p * 2] = make_uint4(ah0, al0, ah1, al1);
                const float b0 = bv[p * 2], b1 = bv[p * 2 + 1];
                uint32_t bh0 = f2tf(b0), bh1 = f2tf(b1);
                uint32_t bl0 = f2tf(b0 - __uint_as_float(bh0));
                uint32_t bl1 = f2tf(b1 - __uint_as_float(bh1));
                *(uint4*)&Bs2[t][u * 4 + p * 2] = make_uint4(bh0, bl0, bh1, bl1);
            }
        }
        __syncthreads();

        // ---- prefetch next tile ----
        if (k0 + BK < K) {
#pragma unroll
            for (int u = 0; u < 4; u++) {
                pa[u] = *(const float4*)(arow + k0 + BK + u * 4);
                pb[u] = *(const float4*)(wrow + k0 + BK + u * 4);
            }
        }

        // ---- compute 2 k8-steps ----
#pragma unroll
        for (int kk = 0; kk < 2; kk++) {
            const int kc0 = kk * 8 + t4;
            const int kc1 = kc0 + 4;
            // A fragments: 16 LDS.64
            uint32_t ahi[4][4], alo[4][4];
#pragma unroll
            for (int mt = 0; mt < 4; mt++) {
                const int r0 = wm * 64 + mt * 16 + g;
                uint2 v0 = As2[r0][kc0];
                uint2 v1 = As2[r0 + 8][kc0];
                uint2 v2 = As2[r0][kc1];
                uint2 v3 = As2[r0 + 8][kc1];
                ahi[mt][0] = v0.x; alo[mt][0] = v0.y;
                ahi[mt][1] = v1.x; alo[mt][1] = v1.y;
                ahi[mt][2] = v2.x; alo[mt][2] = v2.y;
                ahi[mt][3] = v3.x; alo[mt][3] = v3.y;
            }
            // B in two halves of 4 n-tiles to cap register pressure
#pragma unroll
            for (int h = 0; h < 2; h++) {
                uint32_t bhi[4][2], blo[4][2];
#pragma unroll
                for (int nt = 0; nt < 4; nt++) {
                    const int n0 = wn * 64 + (h * 4 + nt) * 8 + g;
                    uint2 u0 = Bs2[n0][kc0];
                    uint2 u1 = Bs2[n0][kc1];
                    bhi[nt][0] = u0.x; blo[nt][0] = u0.y;
                    bhi[nt][1] = u1.x; blo[nt][1] = u1.y;
                }
                // pass-major: hh, hl, lh (acc reuse distance = 16 mmas)
#pragma unroll
                for (int mt = 0; mt < 4; mt++)
#pragma unroll
                    for (int nt = 0; nt < 4; nt++)
                        mma_tf32(acc[mt][h * 4 + nt],
                                 ahi[mt][0], ahi[mt][1], ahi[mt][2], ahi[mt][3],
                                 bhi[nt][0], bhi[nt][1]);
#pragma unroll
                for (int mt = 0; mt < 4; mt++)
#pragma unroll
                    for (int nt = 0; nt < 4; nt++)
                        mma_tf32(acc[mt][h * 4 + nt],
                                 ahi[mt][0], ahi[mt][1], ahi[mt][2], ahi[mt][3],
                                 blo[nt][0], blo[nt][1]);
#pragma unroll
                for (int mt = 0; mt < 4; mt++)
#pragma unroll
                    for (int nt = 0; nt < 4; nt++)
                        mma_tf32(acc[mt][h * 4 + nt],
                                 alo[mt][0], alo[mt][1], alo[mt][2], alo[mt][3],
                                 bhi[nt][0], bhi[nt][1]);
            }
        }
        __syncthreads();
    }

    // ---- epilogue ----
#pragma unroll
    for (int mt = 0; mt < 4; mt++) {
#pragma unroll
        for (int nt = 0; nt < 8; nt++) {
            const int m0 = block_m + wm * 64 + mt * 16 + g;
            const int n0 = block_n + wn * 64 + nt * 8 + t4 * 2;
            const float bv0 = bias[n0], bv1 = bias[n0 + 1];
            if (m0 < M) {
                float2 o = make_float2(acc[mt][nt][0] + bv0, acc[mt][nt][1] + bv1);
                *(float2*)&C[(size_t)m0 * N + n0] = o;
            }
            if (m0 + 8 < M) {
                float2 o = make_float2(acc[mt][nt][2] + bv0, acc[mt][nt][3] + bv1);
                *(float2*)&C[(size_t)(m0 + 8) * N + n0] = o;
            }
        }
    }
}

static void run_gemm(const float* A, const float* W, const float* b, float* C,
                     int M, int N, int K)
{
    dim3 grid(N / BN, (M + BM - 1) / BM);
    gemm_tf32_kernel<<<grid, 128>>>(A, W, b, C, M, N, K);
}

// ---------------------------------------------------------------------------
// Softmax / segment machinery
// ---------------------------------------------------------------------------
__device__ __forceinline__ void atomicMaxFloat(float* addr, float val)
{
    if (val >= 0.f)
        atomicMax((int*)addr, __float_as_int(val));
    else
        atomicMin((unsigned int*)addr, __float_as_uint(val));
}

__global__ void init_pass_kernel(float* segmax, float* segsum, int* counts, int nseg)
{
    int i = blockIdx.x * blockDim.x + threadIdx.x;
    if (i < nseg) {
        segmax[i] = -INFINITY;
        segsum[i] = 0.f;
        counts[i] = 0;
    }
}

__global__ __launch_bounds__(256) void score_kernel(
    const float* __restrict__ kmat, const float* __restrict__ qmat,
    const int* __restrict__ kidx, const int* __restrict__ qidx,
    const int* __restrict__ seg,
    float* __restrict__ score, float* __restrict__ segmax, int* __restrict__ counts,
    int nnz)
{
    const int w = (blockIdx.x * blockDim.x + threadIdx.x) >> 5;
    const int lane = threadIdx.x & 31;
    if (w >= nnz) return;
    const int ki = kidx[w];
    const int qi = qidx[w];
    float4 a = *(const float4*)&kmat[(size_t)ki * QDIM + lane * 4];
    float4 b = *(const float4*)&qmat[(size_t)qi * QDIM + lane * 4];
    float d = a.x * b.x + a.y * b.y + a.z * b.z + a.w * b.w;
#pragma unroll
    for (int o = 16; o > 0; o >>= 1) d += __shfl_xor_sync(0xffffffffu, d, o);
    if (lane == 0) {
        float s = (d >= 0.f ? d : NEG_SLOPE * d) * SCORE_SCALE;
        score[w] = s;
        const int sg = seg[w];
        atomicMaxFloat(&segmax[sg], s);
        atomicAdd(&counts[sg], 1);
    }
}

// ---- two-level scan ----
__global__ __launch_bounds__(1024) void scan_block_kernel(
    const int* __restrict__ counts, int* __restrict__ offsets,
    int* __restrict__ partials, int n)
{
    __shared__ int sh[1024];
    const int t = threadIdx.x;
    const int i = blockIdx.x * 1024 + t;
    const int x = (i < n) ? counts[i] : 0;
    sh[t] = x;
    __syncthreads();
    for (int off = 1; off < 1024; off <<= 1) {
        int v = (t >= off) ? sh[t - off] : 0;
        __syncthreads();
        sh[t] += v;
        __syncthreads();
    }
    if (i < n) offsets[i] = sh[t] - x;
    if (t == 1023) partials[blockIdx.x] = sh[1023];
}

__global__ void scan_partials_kernel(int* partials, int* offsets, int nb, int n)
{
    __shared__ int sh[64];
    const int t = threadIdx.x;
    const int x = (t < nb) ? partials[t] : 0;
    sh[t] = x;
    __syncthreads();
    for (int off = 1; off < 64; off <<= 1) {
        int v = (t >= off) ? sh[t - off] : 0;
        __syncthreads();
        sh[t] += v;
        __syncthreads();
    }
    if (t < nb) partials[t] = sh[t] - x;
    if (t == 63) offsets[n] = sh[63];
}

__global__ void scan_add_kernel(int* __restrict__ offsets, int* __restrict__ cursor,
                                const int* __restrict__ partials, int n)
{
    int i = blockIdx.x * blockDim.x + threadIdx.x;
    if (i < n) {
        int v = offsets[i] + partials[i >> 10];
        offsets[i] = v;
        cursor[i] = v;
    }
}

__global__ void build_perm_kernel(const int* __restrict__ seg, int* __restrict__ cursor,
                                  int* __restrict__ perm, int nnz)
{
    int i = blockIdx.x * blockDim.x + threadIdx.x;
    if (i < nnz) {
        int pos = atomicAdd(&cursor[seg[i]], 1);
        perm[pos] = i;
    }
}

__global__ void expsum_kernel(const float* __restrict__ score, const int* __restrict__ seg,
                              const float* __restrict__ segmax, float* __restrict__ expw,
                              float* __restrict__ segsum, int nnz)
{
    int i = blockIdx.x * blockDim.x + threadIdx.x;
    if (i < nnz) {
        const int sg = seg[i];
        float e = expf(score[i] - segmax[sg]);
        expw[i] = e;
        atomicAdd(&segsum[sg], e);
    }
}

__global__ __launch_bounds__(256) void aggregate_kernel(
    const float* __restrict__ vmat,
    const int* __restrict__ rowidx,
    const int* __restrict__ offsets, const int* __restrict__ perm,
    const float* __restrict__ expw, const float* __restrict__ segsum,
    float* __restrict__ out, int nseg)
{
    __shared__ int   sh_r[128];
    __shared__ float sh_w[128];
    const int s = blockIdx.x;
    if (s >= nseg) return;
    const int d = threadIdx.x;
    const int beg = offsets[s];
    const int end = offsets[s + 1];
    float acc = 0.f;
    for (int cb = beg; cb < end; cb += 128) {
        const int m = min(128, end - cb);
        if (d < m) {
            const int nz = perm[cb + d];
            sh_w[d] = expw[nz];
            sh_r[d] = rowidx[nz];
        }
        __syncthreads();
        for (int j = 0; j < m; j++)
            acc += sh_w[j] * vmat[(size_t)sh_r[j] * 256 + d];
        __syncthreads();
    }
    const float denom = fmaxf(segsum[s], 1e-20f);
    out[(size_t)s * 256 + d] = fmaxf(acc / denom, 0.f);
}

// ---------------------------------------------------------------------------
// Launch
// ---------------------------------------------------------------------------
extern "C" void kernel_launch(void* const* d_in, const int* in_sizes, int n_in,
                              void* d_out, int out_size)
{
    const float* vfeat    = (const float*)d_in[0];
    const float* efeat    = (const float*)d_in[1];
    const int*   node_idx = (const int*)d_in[2];
    const int*   edge_idx = (const int*)d_in[3];
    const float* W_vtx = (const float*)d_in[4];  const float* b_vtx = (const float*)d_in[5];
    const float* W_qe  = (const float*)d_in[6];  const float* b_qe  = (const float*)d_in[7];
    const float* W_kv  = (const float*)d_in[8];  const float* b_kv  = (const float*)d_in[9];
    const float* W_vv  = (const float*)d_in[10]; const float* b_vv  = (const float*)d_in[11];
    const float* W_qv  = (const float*)d_in[12]; const float* b_qv  = (const float*)d_in[13];
    const float* W_ke  = (const float*)d_in[14]; const float* b_ke  = (const float*)d_in[15];
    const float* W_ve  = (const float*)d_in[16]; const float* b_ve  = (const float*)d_in[17];

    float* out_v = (float*)d_out;
    float* out_e = out_v + (size_t)N_NODES * VDIM;

    float *feat_v, *k1, *v1, *q2, *q1, *k2, *v2, *score, *expw, *segmax, *segsum;
    int *counts, *offsets, *cursor, *perm, *partials;
    cudaGetSymbolAddress((void**)&feat_v, g_feat_v);
    cudaGetSymbolAddress((void**)&k1, g_k1);
    cudaGetSymbolAddress((void**)&v1, g_v1);
    cudaGetSymbolAddress((void**)&q2, g_q2);
    cudaGetSymbolAddress((void**)&q1, g_q1);
    cudaGetSymbolAddress((void**)&k2, g_k2);
    cudaGetSymbolAddress((void**)&v2, g_v2);
    cudaGetSymbolAddress((void**)&score, g_score);
    cudaGetSymbolAddress((void**)&expw, g_expw);
    cudaGetSymbolAddress((void**)&segmax, g_segmax);
    cudaGetSymbolAddress((void**)&segsum, g_segsum);
    cudaGetSymbolAddress((void**)&counts, g_counts);
    cudaGetSymbolAddress((void**)&offsets, g_offsets);
    cudaGetSymbolAddress((void**)&cursor, g_cursor);
    cudaGetSymbolAddress((void**)&perm, g_perm);
    cudaGetSymbolAddress((void**)&partials, g_partials);

    const int scoreBlocks = (NNZ * 32 + 255) / 256;
    const int nnzBlocks   = (NNZ + 255) / 256;

    // ---- projections ----
    run_gemm(vfeat,  W_vtx, b_vtx, feat_v, N_NODES, VDIM, KIN);
    run_gemm(feat_v, W_kv,  b_kv,  k1,     N_NODES, QDIM, VDIM);
    run_gemm(feat_v, W_vv,  b_vv,  v1,     N_NODES, EDIM, VDIM);
    run_gemm(feat_v, W_qv,  b_qv,  q2,     N_NODES, QDIM, VDIM);
    run_gemm(efeat,  W_qe,  b_qe,  q1,     N_EDGES, QDIM, KIN);

    // ---- pass 1: nodes -> hyperedges ----
    {
        const int nseg = N_EDGES;
        const int nb = (nseg + 1023) / 1024;
        init_pass_kernel<<<(nseg + 255) / 256, 256>>>(segmax, segsum, counts, nseg);
        score_kernel<<<scoreBlocks, 256>>>(k1, q1, node_idx, edge_idx, edge_idx,
                                           score, segmax, counts, NNZ);
        scan_block_kernel<<<nb, 1024>>>(counts, offsets, partials, nseg);
        scan_partials_kernel<<<1, 64>>>(partials, offsets, nb, nseg);
        scan_add_kernel<<<(nseg + 255) / 256, 256>>>(offsets, cursor, partials, nseg);
        build_perm_kernel<<<nnzBlocks, 256>>>(edge_idx, cursor, perm, NNZ);
        expsum_kernel<<<nnzBlocks, 256>>>(score, edge_idx, segmax, expw, segsum, NNZ);
        aggregate_kernel<<<nseg, 256>>>(v1, node_idx, offsets, perm, expw, segsum,
                                        out_e, nseg);
    }

    // ---- edge-side projections from feat_e ----
    run_gemm(out_e, W_ke, b_ke, k2, N_EDGES, QDIM, EDIM);
    run_gemm(out_e, W_ve, b_ve, v2, N_EDGES, VDIM, EDIM);

    // ---- pass 2: hyperedges -> nodes ----
    {
        const int nseg = N_NODES;
        const int nb = (nseg + 1023) / 1024;
        init_pass_kernel<<<(nseg + 255) / 256, 256>>>(segmax, segsum, counts, nseg);
        score_kernel<<<scoreBlocks, 256>>>(k2, q2, edge_idx, node_idx, node_idx,
                                           score, segmax, counts, NNZ);
        scan_block_kernel<<<nb, 1024>>>(counts, offsets, partials, nseg);
        scan_partials_kernel<<<1, 64>>>(partials, offsets, nb, nseg);
        scan_add_kernel<<<(nseg + 255) / 256, 256>>>(offsets, cursor, partials, nseg);
        build_perm_kernel<<<nnzBlocks, 256>>>(node_idx, cursor, perm, NNZ);
        expsum_kernel<<<nnzBlocks, 256>>>(score, node_idx, segmax, expw, segsum, NNZ);
        aggregate_kernel<<<nseg, 256>>>(v2, edge_idx, offsets, perm, expw, segsum,
                                        out_v, nseg);
    }
}

// round 5
// speedup vs baseline: 1.5133x; 1.5133x over previous
#include <cuda_runtime.h>
#include <cuda_bf16.h>
#include <math.h>
#include <stdint.h>

// ---------------------------------------------------------------------------
// Problem constants
// ---------------------------------------------------------------------------
#define N_NODES 50000
#define N_EDGES 10000
#define NNZ     400000
#define QDIM    128
#define VDIM    256
#define EDIM    256
#define KIN     256
#define NEG_SLOPE 0.01f
#define SCORE_SCALE 0.08838834764831845f   // 1/sqrt(128)

// ---------------------------------------------------------------------------
// Static scratch (no allocation allowed)
// ---------------------------------------------------------------------------
__device__ float g_feat_v[N_NODES * VDIM];
__device__ float g_k1[N_NODES * QDIM];
__device__ float g_v1[N_NODES * EDIM];
__device__ float g_q2[N_NODES * QDIM];
__device__ float g_q1[N_EDGES * QDIM];
__device__ float g_k2[N_EDGES * QDIM];
__device__ float g_v2[N_EDGES * VDIM];
__device__ float g_score[NNZ];
__device__ float g_expw[NNZ];
__device__ float g_segmax[N_NODES];
__device__ float g_segsum[N_NODES];
__device__ int   g_counts[N_NODES];
__device__ int   g_offsets[N_NODES + 1];
__device__ int   g_cursor[N_NODES];
__device__ int   g_perm[NNZ];
__device__ int   g_partials[64];

// ---------------------------------------------------------------------------
// bf16-split tensor-core GEMM: C[M,N] = A[M,K] @ W[N,K]^T + bias[N]
// x = bf16(x) + bf16(x - bf16(x)); compute hh + hl + lh on
// mma.sync.m16n8k16.bf16 (fp32 accum). Error ~2^-16 per input -> rel ~1e-5.
// Block 128x64, BK=32, 256 threads = 8 warps (4m x 2n), warp tile 32x32.
// SMEM: uint2 per k-pair = (hi0|hi1<<16, lo0|lo1<<16); row stride 20 uint2
// -> fragment LDS.64 conflict-free (addr%128 = 32*(r%4) + 8*pair).
// Requires N % 64 == 0, K % 32 == 0 (true for all calls). M guarded.
// ---------------------------------------------------------------------------
#define BM 128
#define BN 64
#define BK 32
#define SS2 20   // row stride in uint2 units

__device__ __forceinline__ void mma_bf16(float* c,
    uint32_t a0, uint32_t a1, uint32_t a2, uint32_t a3,
    uint32_t b0, uint32_t b1)
{
    asm volatile(
        "mma.sync.aligned.m16n8k16.row.col.f32.bf16.bf16.f32 "
        "{%0,%1,%2,%3}, {%4,%5,%6,%7}, {%8,%9}, {%0,%1,%2,%3};"
        : "+f"(c[0]), "+f"(c[1]), "+f"(c[2]), "+f"(c[3])
        : "r"(a0), "r"(a1), "r"(a2), "r"(a3), "r"(b0), "r"(b1));
}

// convert 2 consecutive f32 -> (hi-pair, lo-pair) packed words
__device__ __forceinline__ uint2 split2(float x0, float x1)
{
    __nv_bfloat16 h0 = __float2bfloat16_rn(x0);
    __nv_bfloat16 h1 = __float2bfloat16_rn(x1);
    __nv_bfloat16 l0 = __float2bfloat16_rn(x0 - __bfloat162float(h0));
    __nv_bfloat16 l1 = __float2bfloat16_rn(x1 - __bfloat162float(h1));
    uint2 r;
    r.x = (uint32_t)__bfloat16_as_ushort(h0) | ((uint32_t)__bfloat16_as_ushort(h1) << 16);
    r.y = (uint32_t)__bfloat16_as_ushort(l0) | ((uint32_t)__bfloat16_as_ushort(l1) << 16);
    return r;
}

__global__ __launch_bounds__(256, 2) void gemm_bf16_kernel(
    const float* __restrict__ A, const float* __restrict__ W,
    const float* __restrict__ bias, float* __restrict__ C,
    int M, int N, int K)
{
    __shared__ uint2 As2[BM][SS2];   // 20.5 KB
    __shared__ uint2 Bs2[BN][SS2];   // 10.25 KB

    const int t    = threadIdx.x;
    const int lane = t & 31;
    const int wid  = t >> 5;
    const int wm   = wid & 3;    // warp m (0..3), 32 rows
    const int wn   = wid >> 2;   // warp n (0..1), 32 cols
    const int g    = lane >> 2;
    const int t4   = lane & 3;

    const int block_m = blockIdx.y * BM;
    const int block_n = blockIdx.x * BN;

    // staging assignment: A: 2 threads/row (16 floats each); B: 4 threads/row (8 floats)
    const int arow_i = t >> 1;
    const int aseg   = (t & 1) * 16;
    const int brow_i = t >> 2;
    const int bseg   = (t & 3) * 8;
    const int gma = block_m + arow_i;
    const float* aptr = A + (size_t)(gma < M ? gma : (M - 1)) * K + aseg;
    const float* bptr = W + (size_t)(block_n + brow_i) * K + bseg;

    float acc[2][4][4];
#pragma unroll
    for (int i = 0; i < 2; i++)
#pragma unroll
        for (int j = 0; j < 4; j++)
#pragma unroll
            for (int l = 0; l < 4; l++) acc[i][j][l] = 0.f;

    float4 pa[4], pb[2];
#pragma unroll
    for (int u = 0; u < 4; u++) pa[u] = *(const float4*)(aptr + u * 4);
#pragma unroll
    for (int u = 0; u < 2; u++) pb[u] = *(const float4*)(bptr + u * 4);

    const int NC = K / BK;
    for (int c = 0; c < NC; c++) {
        // ---- stage current chunk (convert to hi/lo bf16 pairs) ----
#pragma unroll
        for (int u = 0; u < 4; u++) {
            uint2 p0 = split2(pa[u].x, pa[u].y);
            uint2 p1 = split2(pa[u].z, pa[u].w);
            asm volatile("st.shared.v4.b32 [%0], {%1,%2,%3,%4};" ::
                "l"(__cvta_generic_to_shared(&As2[arow_i][aseg / 2 + u * 2])),
                "r"(p0.x), "r"(p0.y), "r"(p1.x), "r"(p1.y) : "memory");
        }
#pragma unroll
        for (int u = 0; u < 2; u++) {
            uint2 p0 = split2(pb[u].x, pb[u].y);
            uint2 p1 = split2(pb[u].z, pb[u].w);
            asm volatile("st.shared.v4.b32 [%0], {%1,%2,%3,%4};" ::
                "l"(__cvta_generic_to_shared(&Bs2[brow_i][bseg / 2 + u * 2])),
                "r"(p0.x), "r"(p0.y), "r"(p1.x), "r"(p1.y) : "memory");
        }
        __syncthreads();

        // ---- prefetch next chunk ----
        if (c + 1 < NC) {
            const int k1o = (c + 1) * BK;
#pragma unroll
            for (int u = 0; u < 4; u++) pa[u] = *(const float4*)(aptr + k1o + u * 4);
#pragma unroll
            for (int u = 0; u < 2; u++) pb[u] = *(const float4*)(bptr + k1o + u * 4);
        }

        // ---- 2 k16-steps ----
#pragma unroll
        for (int kk = 0; kk < 2; kk++) {
            const int kc0 = kk * 8 + t4;
            const int kc1 = kc0 + 4;
            uint32_t ahi[2][4], alo[2][4];
#pragma unroll
            for (int mt = 0; mt < 2; mt++) {
                const int r0 = wm * 32 + mt * 16 + g;
                uint2 v0 = As2[r0][kc0];
                uint2 v1 = As2[r0 + 8][kc0];
                uint2 v2 = As2[r0][kc1];
                uint2 v3 = As2[r0 + 8][kc1];
                ahi[mt][0] = v0.x; alo[mt][0] = v0.y;
                ahi[mt][1] = v1.x; alo[mt][1] = v1.y;
                ahi[mt][2] = v2.x; alo[mt][2] = v2.y;
                ahi[mt][3] = v3.x; alo[mt][3] = v3.y;
            }
            uint32_t bhi[4][2], blo[4][2];
#pragma unroll
            for (int nt = 0; nt < 4; nt++) {
                const int n0 = wn * 32 + nt * 8 + g;
                uint2 u0 = Bs2[n0][kc0];
                uint2 u1 = Bs2[n0][kc1];
                bhi[nt][0] = u0.x; blo[nt][0] = u0.y;
                bhi[nt][1] = u1.x; blo[nt][1] = u1.y;
            }
            // pass-major: hh, hl, lh (acc reuse distance = 8)
#pragma unroll
            for (int mt = 0; mt < 2; mt++)
#pragma unroll
                for (int nt = 0; nt < 4; nt++)
                    mma_bf16(acc[mt][nt], ahi[mt][0], ahi[mt][1], ahi[mt][2], ahi[mt][3],
                             bhi[nt][0], bhi[nt][1]);
#pragma unroll
            for (int mt = 0; mt < 2; mt++)
#pragma unroll
                for (int nt = 0; nt < 4; nt++)
                    mma_bf16(acc[mt][nt], ahi[mt][0], ahi[mt][1], ahi[mt][2], ahi[mt][3],
                             blo[nt][0], blo[nt][1]);
#pragma unroll
            for (int mt = 0; mt < 2; mt++)
#pragma unroll
                for (int nt = 0; nt < 4; nt++)
                    mma_bf16(acc[mt][nt], alo[mt][0], alo[mt][1], alo[mt][2], alo[mt][3],
                             bhi[nt][0], bhi[nt][1]);
        }
        __syncthreads();
    }

    // ---- epilogue ----
#pragma unroll
    for (int mt = 0; mt < 2; mt++) {
#pragma unroll
        for (int nt = 0; nt < 4; nt++) {
            const int m0 = block_m + wm * 32 + mt * 16 + g;
            const int n0 = block_n + wn * 32 + nt * 8 + t4 * 2;
            const float bv0 = bias[n0], bv1 = bias[n0 + 1];
            if (m0 < M) {
                float2 o = make_float2(acc[mt][nt][0] + bv0, acc[mt][nt][1] + bv1);
                *(float2*)&C[(size_t)m0 * N + n0] = o;
            }
            if (m0 + 8 < M) {
                float2 o = make_float2(acc[mt][nt][2] + bv0, acc[mt][nt][3] + bv1);
                *(float2*)&C[(size_t)(m0 + 8) * N + n0] = o;
            }
        }
    }
}

static void run_gemm(const float* A, const float* W, const float* b, float* C,
                     int M, int N, int K)
{
    dim3 grid(N / BN, (M + BM - 1) / BM);
    gemm_bf16_kernel<<<grid, 256>>>(A, W, b, C, M, N, K);
}

// ---------------------------------------------------------------------------
// Softmax / segment machinery
// ---------------------------------------------------------------------------
__device__ __forceinline__ void atomicMaxFloat(float* addr, float val)
{
    if (val >= 0.f)
        atomicMax((int*)addr, __float_as_int(val));
    else
        atomicMin((unsigned int*)addr, __float_as_uint(val));
}

__global__ void init_pass_kernel(float* segmax, float* segsum, int* counts, int nseg)
{
    int i = blockIdx.x * blockDim.x + threadIdx.x;
    if (i < nseg) {
        segmax[i] = -INFINITY;
        segsum[i] = 0.f;
        counts[i] = 0;
    }
}

__global__ __launch_bounds__(256) void score_kernel(
    const float* __restrict__ kmat, const float* __restrict__ qmat,
    const int* __restrict__ kidx, const int* __restrict__ qidx,
    const int* __restrict__ seg,
    float* __restrict__ score, float* __restrict__ segmax, int* __restrict__ counts,
    int nnz)
{
    const int w = (blockIdx.x * blockDim.x + threadIdx.x) >> 5;
    const int lane = threadIdx.x & 31;
    if (w >= nnz) return;
    const int ki = kidx[w];
    const int qi = qidx[w];
    float4 a = *(const float4*)&kmat[(size_t)ki * QDIM + lane * 4];
    float4 b = *(const float4*)&qmat[(size_t)qi * QDIM + lane * 4];
    float d = a.x * b.x + a.y * b.y + a.z * b.z + a.w * b.w;
#pragma unroll
    for (int o = 16; o > 0; o >>= 1) d += __shfl_xor_sync(0xffffffffu, d, o);
    if (lane == 0) {
        float s = (d >= 0.f ? d : NEG_SLOPE * d) * SCORE_SCALE;
        score[w] = s;
        const int sg = seg[w];
        atomicMaxFloat(&segmax[sg], s);
        atomicAdd(&counts[sg], 1);
    }
}

__global__ __launch_bounds__(1024) void scan_block_kernel(
    const int* __restrict__ counts, int* __restrict__ offsets,
    int* __restrict__ partials, int n)
{
    __shared__ int sh[1024];
    const int t = threadIdx.x;
    const int i = blockIdx.x * 1024 + t;
    const int x = (i < n) ? counts[i] : 0;
    sh[t] = x;
    __syncthreads();
    for (int off = 1; off < 1024; off <<= 1) {
        int v = (t >= off) ? sh[t - off] : 0;
        __syncthreads();
        sh[t] += v;
        __syncthreads();
    }
    if (i < n) offsets[i] = sh[t] - x;
    if (t == 1023) partials[blockIdx.x] = sh[1023];
}

__global__ void scan_partials_kernel(int* partials, int* offsets, int nb, int n)
{
    __shared__ int sh[64];
    const int t = threadIdx.x;
    const int x = (t < nb) ? partials[t] : 0;
    sh[t] = x;
    __syncthreads();
    for (int off = 1; off < 64; off <<= 1) {
        int v = (t >= off) ? sh[t - off] : 0;
        __syncthreads();
        sh[t] += v;
        __syncthreads();
    }
    if (t < nb) partials[t] = sh[t] - x;
    if (t == 63) offsets[n] = sh[63];
}

__global__ void scan_add_kernel(int* __restrict__ offsets, int* __restrict__ cursor,
                                const int* __restrict__ partials, int n)
{
    int i = blockIdx.x * blockDim.x + threadIdx.x;
    if (i < n) {
        int v = offsets[i] + partials[i >> 10];
        offsets[i] = v;
        cursor[i] = v;
    }
}

__global__ void build_perm_kernel(const int* __restrict__ seg, int* __restrict__ cursor,
                                  int* __restrict__ perm, int nnz)
{
    int i = blockIdx.x * blockDim.x + threadIdx.x;
    if (i < nnz) {
        int pos = atomicAdd(&cursor[seg[i]], 1);
        perm[pos] = i;
    }
}

__global__ void expsum_kernel(const float* __restrict__ score, const int* __restrict__ seg,
                              const float* __restrict__ segmax, float* __restrict__ expw,
                              float* __restrict__ segsum, int nnz)
{
    int i = blockIdx.x * blockDim.x + threadIdx.x;
    if (i < nnz) {
        const int sg = seg[i];
        float e = expf(score[i] - segmax[sg]);
        expw[i] = e;
        atomicAdd(&segsum[sg], e);
    }
}

__global__ __launch_bounds__(256) void aggregate_kernel(
    const float* __restrict__ vmat,
    const int* __restrict__ rowidx,
    const int* __restrict__ offsets, const int* __restrict__ perm,
    const float* __restrict__ expw, const float* __restrict__ segsum,
    float* __restrict__ out, int nseg)
{
    __shared__ int   sh_r[128];
    __shared__ float sh_w[128];
    const int s = blockIdx.x;
    if (s >= nseg) return;
    const int d = threadIdx.x;
    const int beg = offsets[s];
    const int end = offsets[s + 1];
    float acc = 0.f;
    for (int cb = beg; cb < end; cb += 128) {
        const int m = min(128, end - cb);
        if (d < m) {
            const int nz = perm[cb + d];
            sh_w[d] = expw[nz];
            sh_r[d] = rowidx[nz];
        }
        __syncthreads();
        for (int j = 0; j < m; j++)
            acc += sh_w[j] * vmat[(size_t)sh_r[j] * 256 + d];
        __syncthreads();
    }
    const float denom = fmaxf(segsum[s], 1e-20f);
    out[(size_t)s * 256 + d] = fmaxf(acc / denom, 0.f);
}

// ---------------------------------------------------------------------------
// Launch
// ---------------------------------------------------------------------------
extern "C" void kernel_launch(void* const* d_in, const int* in_sizes, int n_in,
                              void* d_out, int out_size)
{
    const float* vfeat    = (const float*)d_in[0];
    const float* efeat    = (const float*)d_in[1];
    const int*   node_idx = (const int*)d_in[2];
    const int*   edge_idx = (const int*)d_in[3];
    const float* W_vtx = (const float*)d_in[4];  const float* b_vtx = (const float*)d_in[5];
    const float* W_qe  = (const float*)d_in[6];  const float* b_qe  = (const float*)d_in[7];
    const float* W_kv  = (const float*)d_in[8];  const float* b_kv  = (const float*)d_in[9];
    const float* W_vv  = (const float*)d_in[10]; const float* b_vv  = (const float*)d_in[11];
    const float* W_qv  = (const float*)d_in[12]; const float* b_qv  = (const float*)d_in[13];
    const float* W_ke  = (const float*)d_in[14]; const float* b_ke  = (const float*)d_in[15];
    const float* W_ve  = (const float*)d_in[16]; const float* b_ve  = (const float*)d_in[17];

    float* out_v = (float*)d_out;
    float* out_e = out_v + (size_t)N_NODES * VDIM;

    float *feat_v, *k1, *v1, *q2, *q1, *k2, *v2, *score, *expw, *segmax, *segsum;
    int *counts, *offsets, *cursor, *perm, *partials;
    cudaGetSymbolAddress((void**)&feat_v, g_feat_v);
    cudaGetSymbolAddress((void**)&k1, g_k1);
    cudaGetSymbolAddress((void**)&v1, g_v1);
    cudaGetSymbolAddress((void**)&q2, g_q2);
    cudaGetSymbolAddress((void**)&q1, g_q1);
    cudaGetSymbolAddress((void**)&k2, g_k2);
    cudaGetSymbolAddress((void**)&v2, g_v2);
    cudaGetSymbolAddress((void**)&score, g_score);
    cudaGetSymbolAddress((void**)&expw, g_expw);
    cudaGetSymbolAddress((void**)&segmax, g_segmax);
    cudaGetSymbolAddress((void**)&segsum, g_segsum);
    cudaGetSymbolAddress((void**)&counts, g_counts);
    cudaGetSymbolAddress((void**)&offsets, g_offsets);
    cudaGetSymbolAddress((void**)&cursor, g_cursor);
    cudaGetSymbolAddress((void**)&perm, g_perm);
    cudaGetSymbolAddress((void**)&partials, g_partials);

    const int scoreBlocks = (NNZ * 32 + 255) / 256;
    const int nnzBlocks   = (NNZ + 255) / 256;

    // ---- projections ----
    run_gemm(vfeat,  W_vtx, b_vtx, feat_v, N_NODES, VDIM, KIN);
    run_gemm(feat_v, W_kv,  b_kv,  k1,     N_NODES, QDIM, VDIM);
    run_gemm(feat_v, W_vv,  b_vv,  v1,     N_NODES, EDIM, VDIM);
    run_gemm(feat_v, W_qv,  b_qv,  q2,     N_NODES, QDIM, VDIM);
    run_gemm(efeat,  W_qe,  b_qe,  q1,     N_EDGES, QDIM, KIN);

    // ---- pass 1: nodes -> hyperedges ----
    {
        const int nseg = N_EDGES;
        const int nb = (nseg + 1023) / 1024;
        init_pass_kernel<<<(nseg + 255) / 256, 256>>>(segmax, segsum, counts, nseg);
        score_kernel<<<scoreBlocks, 256>>>(k1, q1, node_idx, edge_idx, edge_idx,
                                           score, segmax, counts, NNZ);
        scan_block_kernel<<<nb, 1024>>>(counts, offsets, partials, nseg);
        scan_partials_kernel<<<1, 64>>>(partials, offsets, nb, nseg);
        scan_add_kernel<<<(nseg + 255) / 256, 256>>>(offsets, cursor, partials, nseg);
        build_perm_kernel<<<nnzBlocks, 256>>>(edge_idx, cursor, perm, NNZ);
        expsum_kernel<<<nnzBlocks, 256>>>(score, edge_idx, segmax, expw, segsum, NNZ);
        aggregate_kernel<<<nseg, 256>>>(v1, node_idx, offsets, perm, expw, segsum,
                                        out_e, nseg);
    }

    // ---- edge-side projections from feat_e ----
    run_gemm(out_e, W_ke, b_ke, k2, N_EDGES, QDIM, EDIM);
    run_gemm(out_e, W_ve, b_ve, v2, N_EDGES, VDIM, EDIM);

    // ---- pass 2: hyperedges -> nodes ----
    {
        const int nseg = N_NODES;
        const int nb = (nseg + 1023) / 1024;
        init_pass_kernel<<<(nseg + 255) / 256, 256>>>(segmax, segsum, counts, nseg);
        score_kernel<<<scoreBlocks, 256>>>(k2, q2, edge_idx, node_idx, node_idx,
                                           score, segmax, counts, NNZ);
        scan_block_kernel<<<nb, 1024>>>(counts, offsets, partials, nseg);
        scan_partials_kernel<<<1, 64>>>(partials, offsets, nb, nseg);
        scan_add_kernel<<<(nseg + 255) / 256, 256>>>(offsets, cursor, partials, nseg);
        build_perm_kernel<<<nnzBlocks, 256>>>(node_idx, cursor, perm, NNZ);
        expsum_kernel<<<nnzBlocks, 256>>>(score, node_idx, segmax, expw, segsum, NNZ);
        aggregate_kernel<<<nseg, 256>>>(v2, edge_idx, offsets, perm, expw, segsum,
                                        out_v, nseg);
    }
}